// round 9
// baseline (speedup 1.0000x reference)
#include <cuda_runtime.h>
#include <cuda_fp16.h>
#include <cstdint>

// LinearAttend: q,k,v [4][8][64][8192] f32 -> out same shape.
//   ks = softmax(k, axis=s); qs = softmax(q, axis=d) * D^-0.5
//   ctx = ks @ v^T (64x64/head); out = ctx^T @ qs
// fp16 m16n8k16 MMA (fp32 accum), ldmatrix feed, ex2.approx.f16x2 exps,
// Zk via ones-column MMA, atomic-free split-K partials.
// This round: out_kernel gets cp.async staging (no register-coupled q loads);
// ctx CHUNKS 16 for work-steal balance.

#define SQ 8192
#define DH 64
#define NHEADS 32
#define CHUNKS 16
#define CHUNK_S (SQ / CHUNKS)     // 512 -> 8 tiles of 64
#define LOG2E 1.4426950408889634f

__device__ float  g_ctx_part[CHUNKS * NHEADS * DH * DH];  // 8 MB partials
__device__ float  g_zk_part[CHUNKS * NHEADS * DH];
__device__ __half g_ctxh[NHEADS * DH * DH];               // normalized ctx

__device__ __forceinline__ uint32_t smem_u32(const void* p) {
    return (uint32_t)__cvta_generic_to_shared(p);
}
__device__ __forceinline__ void cp_async16(uint32_t dst, const void* src) {
    asm volatile("cp.async.cg.shared.global [%0], [%1], 16;" :: "r"(dst), "l"(src));
}
__device__ __forceinline__ void cp_commit() {
    asm volatile("cp.async.commit_group;");
}
__device__ __forceinline__ void cp_wait1() {
    asm volatile("cp.async.wait_group 1;");
}
__device__ __forceinline__ void cp_wait0() {
    asm volatile("cp.async.wait_group 0;");
}
__device__ __forceinline__ void ldsm_x4(uint32_t* r, uint32_t a) {
    asm volatile("ldmatrix.sync.aligned.m8n8.x4.shared.b16 {%0,%1,%2,%3}, [%4];"
                 : "=r"(r[0]), "=r"(r[1]), "=r"(r[2]), "=r"(r[3]) : "r"(a));
}
__device__ __forceinline__ void ldsm_x2(uint32_t* r, uint32_t a) {
    asm volatile("ldmatrix.sync.aligned.m8n8.x2.shared.b16 {%0,%1}, [%2];"
                 : "=r"(r[0]), "=r"(r[1]) : "r"(a));
}
__device__ __forceinline__ void ldsm_x4t(uint32_t* r, uint32_t a) {
    asm volatile("ldmatrix.sync.aligned.m8n8.x4.trans.shared.b16 {%0,%1,%2,%3}, [%4];"
                 : "=r"(r[0]), "=r"(r[1]), "=r"(r[2]), "=r"(r[3]) : "r"(a));
}
__device__ __forceinline__ void mma_f16(float* d, const uint32_t* a, const uint32_t* b) {
    asm volatile(
        "mma.sync.aligned.m16n8k16.row.col.f32.f16.f16.f32 "
        "{%0,%1,%2,%3}, {%4,%5,%6,%7}, {%8,%9}, {%0,%1,%2,%3};"
        : "+f"(d[0]), "+f"(d[1]), "+f"(d[2]), "+f"(d[3])
        : "r"(a[0]), "r"(a[1]), "r"(a[2]), "r"(a[3]), "r"(b[0]), "r"(b[1]));
}
__device__ __forceinline__ uint32_t pack_h2(float hi, float lo) {
    uint32_t h;
    asm("cvt.rn.f16x2.f32 %0, %1, %2;" : "=r"(h) : "f"(hi), "f"(lo));
    return h;
}
__device__ __forceinline__ uint32_t ex2_h2(uint32_t y) {
    uint32_t r;
    asm("ex2.approx.f16x2 %0, %1;" : "=r"(r) : "r"(y));
    return r;
}

// ---------------------------------------------------------------------------
// Kernel 1: ctx partials. grid (CHUNKS, NHEADS), block 256.
// cp.async 2-stage staging, one barrier per tile.
// ---------------------------------------------------------------------------
#define CTX_SVF_OFF 32768
#define CTX_SA_OFF  65536
#define CTX_SB_OFF  83968
#define CTX_SMEM    104704

__global__ __launch_bounds__(256, 2) void ctx_kernel(const float* __restrict__ k,
                                                     const float* __restrict__ v) {
    extern __shared__ char dyn[];
    float* sKf = reinterpret_cast<float*>(dyn);
    float* sVf = reinterpret_cast<float*>(dyn + CTX_SVF_OFF);
    __half (*sAb)[72] = reinterpret_cast<__half(*)[72]>(dyn + CTX_SA_OFF);
    __half (*sBb)[72] = reinterpret_cast<__half(*)[72]>(dyn + CTX_SB_OFF);

    const int head = blockIdx.y;
    const int s0   = blockIdx.x * CHUNK_S;
    const int tid  = threadIdx.x;
    const int warp = tid >> 5;
    const int lane = tid & 31;
    const int wi   = warp & 3;
    const int wn   = warp >> 2;

    const float* kg = k + (size_t)head * DH * SQ;
    const float* vg = v + (size_t)head * DH * SQ;

    for (int e = tid; e < 2 * 8 * 36; e += 256) {
        const int stg = e / (8 * 36);
        const int rem = e % (8 * 36);
        const int row = 64 + rem / 36;
        *reinterpret_cast<uint32_t*>(&sBb[stg * 72 + row][(rem % 36) * 2]) =
            (row == 64) ? 0x3C003C00u : 0u;
    }

    const int r0 = tid >> 4;
    const int c4 = (tid & 15) * 4;

#pragma unroll
    for (int st = 0; st < 2; ++st) {
        const int scol = s0 + st * 64 + c4;
#pragma unroll
        for (int ib = 0; ib < 4; ++ib) {
            const int row = ib * 16 + r0;
            cp_async16(smem_u32(sKf + st * 4096 + row * 64 + c4), kg + (size_t)row * SQ + scol);
            cp_async16(smem_u32(sVf + st * 4096 + row * 64 + c4), vg + (size_t)row * SQ + scol);
        }
        cp_commit();
    }

    float acc[4][4];
#pragma unroll
    for (int n = 0; n < 4; ++n)
#pragma unroll
        for (int c = 0; c < 4; ++c) acc[n][c] = 0.0f;
    float accz[4] = {0.f, 0.f, 0.f, 0.f};

    const int NT = CHUNK_S / 64;    // 8
    for (int t = 0; t < NT; ++t) {
        const int st = t & 1;
        __half (*sA)[72] = sAb + st * 64;
        __half (*sB)[72] = sBb + st * 72;

        cp_wait1();

        const float* kf = sKf + st * 4096;
        const float* vf = sVf + st * 4096;
#pragma unroll
        for (int ib = 0; ib < 4; ++ib) {
            const int row = ib * 16 + r0;
            float4 kv = *reinterpret_cast<const float4*>(kf + row * 64 + c4);
            float4 vv = *reinterpret_cast<const float4*>(vf + row * 64 + c4);
            uint2 ek;
            ek.x = ex2_h2(pack_h2(kv.y * LOG2E, kv.x * LOG2E));
            ek.y = ex2_h2(pack_h2(kv.w * LOG2E, kv.z * LOG2E));
            *reinterpret_cast<uint2*>(&sA[row][c4]) = ek;
            uint2 vh;
            vh.x = pack_h2(vv.y, vv.x);
            vh.y = pack_h2(vv.w, vv.z);
            *reinterpret_cast<uint2*>(&sB[row][c4]) = vh;
        }

        if (t + 2 < NT) {
            const int scol = s0 + (t + 2) * 64 + c4;
#pragma unroll
            for (int ib = 0; ib < 4; ++ib) {
                const int row = ib * 16 + r0;
                cp_async16(smem_u32(sKf + st * 4096 + row * 64 + c4), kg + (size_t)row * SQ + scol);
                cp_async16(smem_u32(sVf + st * 4096 + row * 64 + c4), vg + (size_t)row * SQ + scol);
            }
        }
        cp_commit();

        __syncthreads();

#pragma unroll
        for (int kk = 0; kk < 4; ++kk) {
            uint32_t a[4];
            ldsm_x4(a, smem_u32(&sA[wi * 16 + (lane & 15)]
                                  [kk * 16 + (lane >> 4) * 8]));
#pragma unroll
            for (int np = 0; np < 2; ++np) {
                uint32_t b[4];
                ldsm_x4(b, smem_u32(&sB[wn * 32 + (np * 2 + (lane >> 4)) * 8 + (lane & 7)]
                                      [kk * 16 + ((lane >> 3) & 1) * 8]));
                mma_f16(acc[np * 2],     a, b);
                mma_f16(acc[np * 2 + 1], a, b + 2);
            }
            if (wn == 1) {
                uint32_t b2[2];
                ldsm_x2(b2, smem_u32(&sB[64 + (lane & 7)]
                                       [kk * 16 + ((lane >> 3) & 1) * 8]));
                mma_f16(accz, a, b2);
            }
        }
    }

    float* ctxp = g_ctx_part + ((size_t)blockIdx.x * NHEADS + head) * DH * DH;
    const int i0 = wi * 16 + (lane >> 2);
    const int jb = wn * 32 + (lane & 3) * 2;
#pragma unroll
    for (int n = 0; n < 4; ++n) {
        const int j = jb + n * 8;
        *reinterpret_cast<float2*>(&ctxp[i0 * 64 + j])       = make_float2(acc[n][0], acc[n][1]);
        *reinterpret_cast<float2*>(&ctxp[(i0 + 8) * 64 + j]) = make_float2(acc[n][2], acc[n][3]);
    }
    if (wn == 1 && (lane & 3) == 0) {
        float* zkp = g_zk_part + ((size_t)blockIdx.x * NHEADS + head) * DH;
        zkp[i0]     = accz[0];
        zkp[i0 + 8] = accz[2];
    }
}

// ---------------------------------------------------------------------------
// Kernel 1.5: sum partials, normalize: ctxh[i][j] = sum_c part[c]*0.125/Zk[i]
// grid NHEADS, block 256.
// ---------------------------------------------------------------------------
__global__ __launch_bounds__(256) void norm_kernel() {
    const int head = blockIdx.x;
    const int tid  = threadIdx.x;
    const int base = tid * 16;
    const int i    = base >> 6;

    float z = 0.0f;
#pragma unroll
    for (int c = 0; c < CHUNKS; ++c)
        z += g_zk_part[((size_t)c * NHEADS + head) * DH + i];
    const float inv = __fdividef(0.125f, z);

    float s[16];
#pragma unroll
    for (int x = 0; x < 16; ++x) s[x] = 0.0f;
#pragma unroll
    for (int c = 0; c < CHUNKS; ++c) {
        const float* p = g_ctx_part + ((size_t)c * NHEADS + head) * DH * DH + base;
#pragma unroll
        for (int x = 0; x < 4; ++x) {
            float4 f = *reinterpret_cast<const float4*>(p + x * 4);
            s[x * 4]     += f.x;
            s[x * 4 + 1] += f.y;
            s[x * 4 + 2] += f.z;
            s[x * 4 + 3] += f.w;
        }
    }
    uint4 o0, o1;
    o0.x = pack_h2(s[1] * inv,  s[0] * inv);
    o0.y = pack_h2(s[3] * inv,  s[2] * inv);
    o0.z = pack_h2(s[5] * inv,  s[4] * inv);
    o0.w = pack_h2(s[7] * inv,  s[6] * inv);
    o1.x = pack_h2(s[9] * inv,  s[8] * inv);
    o1.y = pack_h2(s[11] * inv, s[10] * inv);
    o1.z = pack_h2(s[13] * inv, s[12] * inv);
    o1.w = pack_h2(s[15] * inv, s[14] * inv);
    __half* och = g_ctxh + head * DH * DH + base;
    *reinterpret_cast<uint4*>(och)     = o0;
    *reinterpret_cast<uint4*>(och + 8) = o1;
}

// ---------------------------------------------------------------------------
// Kernel 2: out[j,s] = (1/Zq_s) * sum_i ctxh[i][j] * exp(q[i,s])
// grid (SQ/128, NHEADS), block 256, one 64x128 tile per CTA.
// cp.async q staging (no register-coupled loads), 64.1KB smem -> 3 CTAs/SM.
// dyn smem: sQf[64][128]f | sQ[64][136]h | sCt[64][72]h | sZp[8][132]f | sCs[128]f
// ---------------------------------------------------------------------------
#define OUT_SQH_OFF 32768
#define OUT_SCT_OFF 50176
#define OUT_SZP_OFF 59392
#define OUT_SCS_OFF 63616
#define OUT_SMEM    64128

__global__ __launch_bounds__(256, 3) void out_kernel(const float* __restrict__ q,
                                                     float* __restrict__ out) {
    extern __shared__ char dyn[];
    float* sQf = reinterpret_cast<float*>(dyn);
    __half (*sQ)[136] = reinterpret_cast<__half(*)[136]>(dyn + OUT_SQH_OFF);
    __half (*sCt)[72] = reinterpret_cast<__half(*)[72]>(dyn + OUT_SCT_OFF);
    float (*sZp)[132] = reinterpret_cast<float(*)[132]>(dyn + OUT_SZP_OFF);
    float* sCs = reinterpret_cast<float*>(dyn + OUT_SCS_OFF);

    const int head = blockIdx.y;
    const int s0   = blockIdx.x * 128;
    const int tid  = threadIdx.x;
    const int warp = tid >> 5;
    const int lane = tid & 31;

    const float* qg = q + (size_t)head * DH * SQ + s0;
    const int r  = tid >> 5;          // 0..7
    const int c4 = (tid & 31) * 4;    // 0..124

    // stage the whole 64x128 f32 q tile via cp.async (no register coupling)
#pragma unroll
    for (int ib = 0; ib < 8; ++ib) {
        const int d = ib * 8 + r;
        cp_async16(smem_u32(sQf + d * 128 + c4), qg + (size_t)d * SQ + c4);
    }
    cp_commit();

    // ctx tile from L2: LDG flies while the cp.asyncs stream
    {
        const uint4* src = reinterpret_cast<const uint4*>(g_ctxh + head * DH * DH);
        uint4 c0 = src[tid * 2];
        uint4 c1 = src[tid * 2 + 1];
        const int i = tid >> 2;
        const int j = (tid & 3) * 16;
        *reinterpret_cast<uint4*>(&sCt[i][j])     = c0;
        *reinterpret_cast<uint4*>(&sCt[i][j + 8]) = c1;
    }

    cp_wait0();   // per-thread self-consistent: converts exactly own staged rows

    float4 zp = make_float4(0.f, 0.f, 0.f, 0.f);
#pragma unroll
    for (int ib = 0; ib < 8; ++ib) {
        const int d = ib * 8 + r;
        float4 qv = *reinterpret_cast<const float4*>(sQf + d * 128 + c4);
        uint2 eq;
        eq.x = ex2_h2(pack_h2(qv.y * LOG2E, qv.x * LOG2E));
        eq.y = ex2_h2(pack_h2(qv.w * LOG2E, qv.z * LOG2E));
        *reinterpret_cast<uint2*>(&sQ[d][c4]) = eq;
        float2 e0 = __half22float2(*reinterpret_cast<__half2*>(&eq.x));
        float2 e1 = __half22float2(*reinterpret_cast<__half2*>(&eq.y));
        zp.x += e0.x; zp.y += e0.y; zp.z += e1.x; zp.w += e1.y;
    }
    *reinterpret_cast<float4*>(&sZp[r][c4]) = zp;
    __syncthreads();

    if (tid < 128) {
        float z = 0.0f;
#pragma unroll
        for (int d = 0; d < 8; ++d) z += sZp[d][tid];
        sCs[tid] = __fdividef(1.0f, z);
    }

    float acc[8][4];
#pragma unroll
    for (int n = 0; n < 8; ++n)
#pragma unroll
        for (int c = 0; c < 4; ++c) acc[n][c] = 0.0f;

    const int jw = (warp & 3) * 16;   // j offset
    const int sw = (warp >> 2) * 64;  // s offset

#pragma unroll
    for (int kk = 0; kk < 4; ++kk) {
        uint32_t a[4];
        ldsm_x4t(a, smem_u32(&sCt[kk * 16 + (lane & 7) + (lane >> 4) * 8]
                                [jw + ((lane >> 3) & 1) * 8]));
#pragma unroll
        for (int np = 0; np < 4; ++np) {
            uint32_t b[4];
            ldsm_x4t(b, smem_u32(&sQ[kk * 16 + (lane & 7) + ((lane >> 3) & 1) * 8]
                                    [sw + (np * 2 + (lane >> 4)) * 8]));
            mma_f16(acc[np * 2],     a, b);
            mma_f16(acc[np * 2 + 1], a, b + 2);
        }
    }
    __syncthreads();   // sCs ready (reduce overlapped with MMA issue)

    float* og = out + (size_t)head * DH * SQ + s0;
    const int j0 = jw + (lane >> 2);
    const int sc = (lane & 3) * 2;
#pragma unroll
    for (int n = 0; n < 8; ++n) {
        const int s = sw + n * 8 + sc;
        const float inv0 = sCs[s];
        const float inv1 = sCs[s + 1];
        float2 w0 = make_float2(acc[n][0] * inv0, acc[n][1] * inv1);
        float2 w1 = make_float2(acc[n][2] * inv0, acc[n][3] * inv1);
        *reinterpret_cast<float2*>(og + (size_t)j0 * SQ + s) = w0;
        *reinterpret_cast<float2*>(og + (size_t)(j0 + 8) * SQ + s) = w1;
    }
}

// ---------------------------------------------------------------------------
extern "C" void kernel_launch(void* const* d_in, const int* in_sizes, int n_in,
                              void* d_out, int out_size) {
    const float* q = (const float*)d_in[0];
    const float* k = (const float*)d_in[1];
    const float* v = (const float*)d_in[2];
    float* out = (float*)d_out;

    cudaFuncSetAttribute(ctx_kernel, cudaFuncAttributeMaxDynamicSharedMemorySize, CTX_SMEM);
    cudaFuncSetAttribute(out_kernel, cudaFuncAttributeMaxDynamicSharedMemorySize, OUT_SMEM);

    ctx_kernel<<<dim3(CHUNKS, NHEADS), 256, CTX_SMEM>>>(k, v);
    norm_kernel<<<NHEADS, 256>>>();
    out_kernel<<<dim3(SQ / 128, NHEADS), 256, OUT_SMEM>>>(q, out);
}